// round 16
// baseline (speedup 1.0000x reference)
#include <cuda_runtime.h>
#include <cstdint>
#include <cuda_fp16.h>
#include <mma.h>
using namespace nvcuda;

#define NN   20000
#define EE   320000
#define ET   (EE + NN)
#define DD   512
#define HH   4
#define CC   128
#define OUTD 256
#define FIN  127

// fp16 GEMM tile: block 128x128, KC=64 half, 8 warps (2x4), warp tile 64x32
// A_LDH = 72 halves = 144B = 9 x 16B (odd) -> conflict-free LDSM rows.
// B_LDH = 136 halves = 272B = 17 x 16B (odd) -> conflict-free.
#define KCH   64
#define A_LDH 72
#define B_LDH 136
#define ABUF_H (128 * A_LDH)
#define BBUF_H (KCH * B_LDH)
#define GEMM_SMEM_BYTES ((2 * ABUF_H + 2 * BBUF_H) * 2)

// ---------------- device scratch ----------------
__device__ __half g_xlh[NN * DD];
__device__ float  g_h [NN * DD];
__device__ float  g_hn[NN * DD];
__device__ __half g_xph[NN * 128];
__device__ __half g_w1h[128 * DD];
__device__ __half g_w2h[DD * DD];
__device__ __half g_owh[DD * OUTD];
__device__ __half g_hnh[NN * DD];
__device__ __half g_hh [NN * DD];
__device__ float  g_als[NN * HH];
__device__ float  g_ald[NN * HH];
__device__ int    g_cnt[NN];
__device__ int    g_ptr[NN + 1];
__device__ int    g_cur[NN];
__device__ int    g_csrc[ET];
__device__ float  g_sumf[DD];
__device__ float  g_sqf [DD];
__device__ float  g_scale[DD];
__device__ float  g_shift[DD];

// ---------------- utility kernels ----------------
__global__ void zero_cnt_k() {
    int i = blockIdx.x * blockDim.x + threadIdx.x;
    if (i < NN) g_cnt[i] = 0;
    if (i < DD) { g_sumf[i] = 0.f; g_sqf[i] = 0.f; }
}
__global__ void pack_k(const float* __restrict__ X, const float* __restrict__ pos) {
    int i = blockIdx.x * blockDim.x + threadIdx.x;
    if (i >= NN * 128) return;
    int r = i >> 7, c = i & 127;
    g_xph[i] = __float2half_rn((c < FIN) ? X[r * FIN + c] : pos[r]);
}
__global__ void cvtw_k(const float* __restrict__ W1, const float* __restrict__ W2,
                       const float* __restrict__ OW) {
    int i = blockIdx.x * blockDim.x + threadIdx.x;
    const int n1 = 128 * DD, n2 = DD * DD, n3 = DD * OUTD;
    if (i < n1) g_w1h[i] = __float2half_rn(W1[i]);
    else if (i < n1 + n2) g_w2h[i - n1] = __float2half_rn(W2[i - n1]);
    else if (i < n1 + n2 + n3) g_owh[i - n1 - n2] = __float2half_rn(OW[i - n1 - n2]);
}

// ---------------- CSR build ----------------
__global__ void count_k(const int* __restrict__ ei) {
    int e = blockIdx.x * blockDim.x + threadIdx.x;
    if (e >= ET) return;
    int dst = (e < EE) ? ei[EE + e] : (e - EE);
    atomicAdd(&g_cnt[dst], 1);
}

__global__ void scan_k() {
    __shared__ int sh[1024];
    int t = threadIdx.x;
    const int CH = 20;
    int base = t * CH;
    int s = 0;
#pragma unroll
    for (int i = 0; i < CH; i++) {
        int idx = base + i;
        if (idx < NN) s += g_cnt[idx];
    }
    sh[t] = s;
    __syncthreads();
    for (int off = 1; off < 1024; off <<= 1) {
        int v = (t >= off) ? sh[t - off] : 0;
        __syncthreads();
        sh[t] += v;
        __syncthreads();
    }
    int run = sh[t] - s;
#pragma unroll
    for (int i = 0; i < CH; i++) {
        int idx = base + i;
        if (idx < NN) {
            g_ptr[idx] = run;
            g_cur[idx] = run;
            run += g_cnt[idx];
        }
    }
    if (t == 1023) g_ptr[NN] = sh[1023];
}

__global__ void fill_k(const int* __restrict__ ei) {
    int e = blockIdx.x * blockDim.x + threadIdx.x;
    if (e >= ET) return;
    int src, dst;
    if (e < EE) { src = ei[e]; dst = ei[EE + e]; }
    else        { src = dst = e - EE; }
    int p = atomicAdd(&g_cur[dst], 1);
    g_csrc[p] = src;
}

// ---------------- fp16 tensor-core GEMM (cp.async double-buffer) ----------
__device__ __forceinline__ void cpa16(unsigned int saddr, const void* g, int sz) {
    asm volatile("cp.async.cg.shared.global [%0], [%1], 16, %2;"
                 :: "r"(saddr), "l"(g), "r"(sz));
}

template <typename TC>
__global__ void __launch_bounds__(256, 2) gemm_tc_k(
    const __half* __restrict__ A, const __half* __restrict__ B,
    const float* __restrict__ bias, TC* __restrict__ C,
    int M, int N, int K,
    const float* __restrict__ asrc, const float* __restrict__ adst)
{
    extern __shared__ __half smh[];
    __half* Asb[2] = { smh, smh + ABUF_H };
    __half* Bsb[2] = { smh + 2 * ABUF_H, smh + 2 * ABUF_H + BBUF_H };

    int tid = threadIdx.x;
    int warp = tid >> 5, lane = tid & 31;
    int wm = (warp >> 2) * 64;
    int wn = (warp & 3) * 32;
    int bm = blockIdx.y * 128, bn = blockIdx.x * 128;

    auto loadA = [&](int buf, int k0) {
#pragma unroll
        for (int i = 0; i < 4; i++) {
            int f = tid + i * 256;
            int r = f >> 3, c8 = (f & 7) * 8;
            long grow = bm + r;
            int sz = (grow < M) ? 16 : 0;
            if (grow >= M) grow = M - 1;
            unsigned sa = (unsigned)__cvta_generic_to_shared(Asb[buf] + r * A_LDH + c8);
            cpa16(sa, A + grow * K + k0 + c8, sz);
        }
    };
    auto loadB = [&](int buf, int k0) {
#pragma unroll
        for (int i = 0; i < 4; i++) {
            int f = tid + i * 256;
            int kr = f >> 4, c8 = (f & 15) * 8;
            unsigned sa = (unsigned)__cvta_generic_to_shared(Bsb[buf] + kr * B_LDH + c8);
            cpa16(sa, B + (long)(k0 + kr) * N + bn + c8, 16);
        }
    };

    wmma::fragment<wmma::accumulator, 16, 16, 16, float> c[4][2];
#pragma unroll
    for (int mi = 0; mi < 4; mi++)
#pragma unroll
        for (int ni = 0; ni < 2; ni++)
            wmma::fill_fragment(c[mi][ni], 0.f);

    loadA(0, 0);
    loadB(0, 0);
    asm volatile("cp.async.commit_group;");
    asm volatile("cp.async.wait_group 0;" ::: "memory");
    __syncthreads();

    int nChunks = K / KCH;
    int buf = 0;
    for (int ch = 0; ch < nChunks; ch++) {
        if (ch + 1 < nChunks) {
            loadA(buf ^ 1, (ch + 1) * KCH);
            loadB(buf ^ 1, (ch + 1) * KCH);
            asm volatile("cp.async.commit_group;");
        }
#pragma unroll
        for (int ks = 0; ks < KCH / 16; ks++) {
            wmma::fragment<wmma::matrix_a, 16, 16, 16, __half, wmma::row_major> a[4];
            wmma::fragment<wmma::matrix_b, 16, 16, 16, __half, wmma::row_major> b[2];
#pragma unroll
            for (int mi = 0; mi < 4; mi++)
                wmma::load_matrix_sync(a[mi], Asb[buf] + (wm + mi * 16) * A_LDH + ks * 16, A_LDH);
#pragma unroll
            for (int ni = 0; ni < 2; ni++)
                wmma::load_matrix_sync(b[ni], Bsb[buf] + (ks * 16) * B_LDH + wn + ni * 16, B_LDH);
#pragma unroll
            for (int mi = 0; mi < 4; mi++)
#pragma unroll
                for (int ni = 0; ni < 2; ni++)
                    wmma::mma_sync(c[mi][ni], a[mi], b[ni], c[mi][ni]);
        }
        if (ch + 1 < nChunks) {
            asm volatile("cp.async.wait_group 0;" ::: "memory");
            __syncthreads();
            buf ^= 1;
        }
    }
    __syncthreads();

    // attention-dot accumulators (one head per N-block)
    float* s_al = (float*)smh + 3072;   // [0:128)=s1, [128:256)=s2
    bool do_al = (asrc != nullptr);
    if (do_al) {
        if (tid < 256) s_al[tid] = 0.f;
        __syncthreads();
    }
    int h = blockIdx.x;

    float* bounce = (float*)smh + warp * 320;
    int er = lane >> 1;
    int ec = (lane & 1) * 8;
#pragma unroll
    for (int mi = 0; mi < 4; mi++) {
        float s1p = 0.f, s2p = 0.f;
#pragma unroll
        for (int ni = 0; ni < 2; ni++) {
            wmma::store_matrix_sync(bounce, c[mi][ni], 20, wmma::mem_row_major);
            __syncwarp();
            int grow = bm + wm + mi * 16 + er;
            if (grow < M) {
                int gcol = bn + wn + ni * 16 + ec;
                const float* srcb = &bounce[er * 20 + ec];
                float v[8];
#pragma unroll
                for (int j = 0; j < 8; j++)
                    v[j] = srcb[j] + (bias ? bias[gcol + j] : 0.f);
                if (do_al) {
                    int c0 = wn + ni * 16 + ec;
#pragma unroll
                    for (int j = 0; j < 8; j++) {
                        s1p += v[j] * asrc[h * CC + c0 + j];
                        s2p += v[j] * adst[h * CC + c0 + j];
                    }
                }
                TC* dst = &C[(long)grow * N + gcol];
                if constexpr (sizeof(TC) == 2) {
                    __half2 hb[4];
#pragma unroll
                    for (int j = 0; j < 4; j++)
                        hb[j] = __floats2half2_rn(v[2 * j], v[2 * j + 1]);
                    *(uint4*)dst = *(const uint4*)hb;
                } else {
                    *(float4*)&dst[0] = make_float4(v[0], v[1], v[2], v[3]);
                    *(float4*)&dst[4] = make_float4(v[4], v[5], v[6], v[7]);
                }
            }
            __syncwarp();
        }
        if (do_al) {
            s1p += __shfl_xor_sync(0xffffffffu, s1p, 1);
            s2p += __shfl_xor_sync(0xffffffffu, s2p, 1);
            if ((lane & 1) == 0) {
                int r = wm + mi * 16 + er;
                atomicAdd(&s_al[r], s1p);
                atomicAdd(&s_al[128 + r], s2p);
            }
        }
    }
    if (do_al) {
        __syncthreads();
        if (tid < 128) {
            int grow = bm + tid;
            if (grow < M) {
                g_als[grow * HH + h] = s_al[tid];
                g_ald[grow * HH + h] = s_al[128 + tid];
            }
        }
    }
}

// ---------------- aggregation: exp fused, half gathers, x4 unroll ---------
__global__ void agg_k(const __half* __restrict__ xlh, const float* __restrict__ bias,
                      float* __restrict__ out)
{
    int n = blockIdx.x;
    int t = threadIdx.x;
    int h = t >> 5;
    int lane = t & 31;
    int p0 = g_ptr[n], p1 = g_ptr[n + 1];
    float ad = g_ald[n * 4 + h];
    float4 acc = make_float4(0.f, 0.f, 0.f, 0.f);
    float s = 0.f;
    const __half* xh = xlh + h * CC + lane * 4;
    int p = p0;
    for (; p + 4 <= p1; p += 4) {
        int sidx[4];
        float w[4];
        uint2 u[4];
#pragma unroll
        for (int q = 0; q < 4; q++) sidx[q] = g_csrc[p + q];
#pragma unroll
        for (int q = 0; q < 4; q++) {
            float v = g_als[sidx[q] * 4 + h] + ad;
            v = v > 0.f ? v : 0.2f * v;
            w[q] = __expf(v);
            u[q] = *(const uint2*)(xh + (long)sidx[q] * DD);
        }
#pragma unroll
        for (int q = 0; q < 4; q++) {
            float2 a0 = __half22float2(*(__half2*)&u[q].x);
            float2 a1 = __half22float2(*(__half2*)&u[q].y);
            s += w[q];
            acc.x += w[q] * a0.x; acc.y += w[q] * a0.y;
            acc.z += w[q] * a1.x; acc.w += w[q] * a1.y;
        }
    }
    for (; p < p1; p++) {
        int sa = g_csrc[p];
        float va = g_als[sa * 4 + h] + ad;
        va = va > 0.f ? va : 0.2f * va;
        float wa = __expf(va);
        uint2 ua = *(const uint2*)(xh + (long)sa * DD);
        float2 a0 = __half22float2(*(__half2*)&ua.x);
        float2 a1 = __half22float2(*(__half2*)&ua.y);
        s += wa;
        acc.x += wa * a0.x; acc.y += wa * a0.y;
        acc.z += wa * a1.x; acc.w += wa * a1.y;
    }
    float inv = 1.f / (s + 1e-16f);
    int col = h * CC + lane * 4;
    float4 bv = *(const float4*)(bias + col);
    float4 o;
    o.x = acc.x * inv + bv.x;
    o.y = acc.y * inv + bv.y;
    o.z = acc.z * inv + bv.z;
    o.w = acc.w * inv + bv.w;
    *(float4*)(out + (long)n * DD + col) = o;
}

// ---------------- batch norm (fp32 stats) ----------------
__global__ void bn_stats_k(const float* __restrict__ h) {
    int t = threadIdx.x;
    int r0 = blockIdx.x * 50;
    float s = 0.f, s2 = 0.f;
    for (int i = 0; i < 50; i++) {
        int r = r0 + i;
        if (r < NN) {
            float v = h[(long)r * DD + t];
            s += v;
            s2 += v * v;
        }
    }
    atomicAdd(&g_sumf[t], s);
    atomicAdd(&g_sqf[t], s2);
}

__global__ void bn_fin_k(const float* __restrict__ g, const float* __restrict__ b) {
    int t = threadIdx.x;
    float mean = g_sumf[t] * (1.f / NN);
    float var  = g_sqf[t] * (1.f / NN) - mean * mean;
    float a = g[t] * rsqrtf(var + 1e-5f);
    g_scale[t] = a;
    g_shift[t] = b[t] - mean * a;
    g_sumf[t] = 0.f;
    g_sqf[t]  = 0.f;
}

__global__ void bn_apply_k(const float4* __restrict__ in, const float4* __restrict__ res,
                           float4* __restrict__ out, __half2* __restrict__ outh)
{
    int i = blockIdx.x * blockDim.x + threadIdx.x;
    if (i >= NN * DD / 4) return;
    int j = (i * 4) & (DD - 1);
    float4 v = in[i];
    v.x = v.x * g_scale[j + 0] + g_shift[j + 0];
    v.y = v.y * g_scale[j + 1] + g_shift[j + 1];
    v.z = v.z * g_scale[j + 2] + g_shift[j + 2];
    v.w = v.w * g_scale[j + 3] + g_shift[j + 3];
    v.x = v.x > 0.f ? v.x : 0.01f * v.x;
    v.y = v.y > 0.f ? v.y : 0.01f * v.y;
    v.z = v.z > 0.f ? v.z : 0.01f * v.z;
    v.w = v.w > 0.f ? v.w : 0.01f * v.w;
    if (res) {
        float4 r = res[i];
        v.x += r.x; v.y += r.y; v.z += r.z; v.w += r.w;
    }
    if (out) out[i] = v;
    outh[i * 2 + 0] = __floats2half2_rn(v.x, v.y);
    outh[i * 2 + 1] = __floats2half2_rn(v.z, v.w);
}

// ---------------- launch ----------------
extern "C" void kernel_launch(void* const* d_in, const int* in_sizes, int n_in,
                              void* d_out, int out_size)
{
    const float* X    = (const float*)d_in[0];
    const int*   ei   = (const int*)d_in[1];
    const float* pos  = (const float*)d_in[3];
    const float* W1   = (const float*)d_in[4];
    const float* as1  = (const float*)d_in[5];
    const float* ad1  = (const float*)d_in[6];
    const float* b1   = (const float*)d_in[7];
    const float* W2   = (const float*)d_in[8];
    const float* as2  = (const float*)d_in[9];
    const float* ad2  = (const float*)d_in[10];
    const float* b2   = (const float*)d_in[11];
    const float* bn1g = (const float*)d_in[12];
    const float* bn1b = (const float*)d_in[13];
    const float* bn2g = (const float*)d_in[14];
    const float* bn2b = (const float*)d_in[15];
    const float* outW = (const float*)d_in[18];
    const float* outb = (const float*)d_in[19];
    float*       out  = (float*)d_out;

    float *h, *hn;
    __half *xlh, *xph, *w1h, *w2h, *owh, *hnh, *hh;
    cudaGetSymbolAddress((void**)&h,   g_h);
    cudaGetSymbolAddress((void**)&hn,  g_hn);
    cudaGetSymbolAddress((void**)&xlh, g_xlh);
    cudaGetSymbolAddress((void**)&xph, g_xph);
    cudaGetSymbolAddress((void**)&w1h, g_w1h);
    cudaGetSymbolAddress((void**)&w2h, g_w2h);
    cudaGetSymbolAddress((void**)&owh, g_owh);
    cudaGetSymbolAddress((void**)&hnh, g_hnh);
    cudaGetSymbolAddress((void**)&hh,  g_hh);

    cudaFuncSetAttribute(gemm_tc_k<__half>, cudaFuncAttributeMaxDynamicSharedMemorySize,
                         GEMM_SMEM_BYTES);
    cudaFuncSetAttribute(gemm_tc_k<float>, cudaFuncAttributeMaxDynamicSharedMemorySize,
                         GEMM_SMEM_BYTES);

    const int EB = (ET + 255) / 256;
    dim3 gGat(DD / 128, (NN + 127) / 128);
    dim3 gOut(OUTD / 128, (NN + 127) / 128);
    int bnApBlocks = (NN * DD / 4 + 255) / 256;
    int bnBlocks = (NN + 49) / 50;
    int nW = 128 * DD + DD * DD + DD * OUTD;

    // side stream: weight conversion + CSR build (independent of pack/gemm1-A)
    cudaStream_t s2;
    cudaStreamCreateWithFlags(&s2, cudaStreamNonBlocking);
    cudaEvent_t eFork, eJoinW, eJoinCSR;
    cudaEventCreateWithFlags(&eFork,    cudaEventDisableTiming);
    cudaEventCreateWithFlags(&eJoinW,   cudaEventDisableTiming);
    cudaEventCreateWithFlags(&eJoinCSR, cudaEventDisableTiming);

    cudaEventRecord(eFork, 0);
    cudaStreamWaitEvent(s2, eFork, 0);

    // side stream: cvtw first (gemm1 needs w1h), then CSR chain
    cvtw_k<<<(nW + 255) / 256, 256, 0, s2>>>(W1, W2, outW);
    cudaEventRecord(eJoinW, s2);
    zero_cnt_k<<<(NN + 255) / 256, 256, 0, s2>>>();
    count_k<<<EB, 256, 0, s2>>>(ei);
    scan_k<<<1, 1024, 0, s2>>>();
    fill_k<<<EB, 256, 0, s2>>>(ei);
    cudaEventRecord(eJoinCSR, s2);

    // main stream
    pack_k<<<(NN * 128 + 255) / 256, 256>>>(X, pos);
    cudaStreamWaitEvent(0, eJoinW, 0);    // gemm1 needs w1h
    gemm_tc_k<__half><<<gGat, 256, GEMM_SMEM_BYTES>>>(xph, w1h, nullptr, xlh,
                                                      NN, DD, 128, as1, ad1);

    cudaStreamWaitEvent(0, eJoinCSR, 0);  // agg needs CSR

    // ---- layer 1 rest ----
    agg_k<<<NN, 128>>>(xlh, b1, h);
    bn_stats_k<<<bnBlocks, 512>>>(h);
    bn_fin_k<<<1, 512>>>(bn1g, bn1b);
    bn_apply_k<<<bnApBlocks, 256>>>((const float4*)h, nullptr, (float4*)hn, (__half2*)hnh);

    // ---- layer 2 ----
    gemm_tc_k<__half><<<gGat, 256, GEMM_SMEM_BYTES>>>(hnh, w2h, nullptr, xlh,
                                                      NN, DD, DD, as2, ad2);
    agg_k<<<NN, 128>>>(xlh, b2, h);
    bn_stats_k<<<bnBlocks, 512>>>(h);
    bn_fin_k<<<1, 512>>>(bn2g, bn2b);
    bn_apply_k<<<bnApBlocks, 256>>>((const float4*)h, (const float4*)hn, nullptr, (__half2*)hh);

    // ---- output projection ----
    gemm_tc_k<float><<<gOut, 256, GEMM_SMEM_BYTES>>>(hh, owh, outb, out,
                                                     NN, OUTD, DD, nullptr, nullptr);

    cudaEventDestroy(eFork);
    cudaEventDestroy(eJoinW);
    cudaEventDestroy(eJoinCSR);
    cudaStreamDestroy(s2);
}

// round 17
// speedup vs baseline: 1.0788x; 1.0788x over previous
#include <cuda_runtime.h>
#include <cstdint>
#include <cuda_fp16.h>
#include <mma.h>
using namespace nvcuda;

#define NN   20000
#define EE   320000
#define ET   (EE + NN)
#define DD   512
#define HH   4
#define CC   128
#define OUTD 256
#define FIN  127

// fp16 GEMM tile: block 128x128, KC=64 half, 8 warps (2x4), warp tile 64x32
// A_LDH = 72 halves = 144B (stride mod 128B distinct per 8 rows) -> conflict-free LDSM.
#define KCH   64
#define A_LDH 72
#define B_LDH 136
#define ABUF_H (128 * A_LDH)
#define BBUF_H (KCH * B_LDH)
#define GEMM_SMEM_BYTES ((2 * ABUF_H + 2 * BBUF_H) * 2)

// ---------------- device scratch ----------------
__device__ __half g_xlh[NN * DD];
__device__ float  g_h [NN * DD];
__device__ float  g_hn[NN * DD];
__device__ __half g_xph[NN * 128];
__device__ __half g_w1h[128 * DD];
__device__ __half g_w2h[DD * DD];
__device__ __half g_owh[DD * OUTD];
__device__ __half g_hnh[NN * DD];
__device__ __half g_hh [NN * DD];
__device__ float  g_als[NN * HH];
__device__ float  g_ald[NN * HH];
__device__ int    g_cnt[NN];
__device__ int    g_ptr[NN + 1];
__device__ int    g_cur[NN];
__device__ int    g_csrc[ET];
__device__ float  g_sumf[DD];
__device__ float  g_sqf [DD];
__device__ float  g_scale[DD];
__device__ float  g_shift[DD];

// ---------------- utility kernels ----------------
__global__ void zero_cnt_k() {
    int i = blockIdx.x * blockDim.x + threadIdx.x;
    if (i < NN) g_cnt[i] = 0;
    if (i < DD) { g_sumf[i] = 0.f; g_sqf[i] = 0.f; }
}
__global__ void pack_k(const float* __restrict__ X, const float* __restrict__ pos) {
    int i = blockIdx.x * blockDim.x + threadIdx.x;
    if (i >= NN * 128) return;
    int r = i >> 7, c = i & 127;
    g_xph[i] = __float2half_rn((c < FIN) ? X[r * FIN + c] : pos[r]);
}
__global__ void cvtw_k(const float* __restrict__ W1, const float* __restrict__ W2,
                       const float* __restrict__ OW) {
    int i = blockIdx.x * blockDim.x + threadIdx.x;
    const int n1 = 128 * DD, n2 = DD * DD, n3 = DD * OUTD;
    if (i < n1) g_w1h[i] = __float2half_rn(W1[i]);
    else if (i < n1 + n2) g_w2h[i - n1] = __float2half_rn(W2[i - n1]);
    else if (i < n1 + n2 + n3) g_owh[i - n1 - n2] = __float2half_rn(OW[i - n1 - n2]);
}

// ---------------- CSR build ----------------
__global__ void count_k(const int* __restrict__ ei) {
    int e = blockIdx.x * blockDim.x + threadIdx.x;
    if (e >= ET) return;
    int dst = (e < EE) ? ei[EE + e] : (e - EE);
    atomicAdd(&g_cnt[dst], 1);
}

// warp-shuffle scan: threads 0..999 each own exactly 20 counts (int4 I/O)
__global__ void scan_k() {
    __shared__ int wsum[32];
    int t = threadIdx.x, lane = t & 31, wid = t >> 5;
    int v[20];
    int s = 0;
    if (t < 1000) {
        const int4* p = (const int4*)(g_cnt + t * 20);
#pragma unroll
        for (int i = 0; i < 5; i++) {
            int4 a = p[i];
            v[i * 4 + 0] = a.x; v[i * 4 + 1] = a.y;
            v[i * 4 + 2] = a.z; v[i * 4 + 3] = a.w;
            s += a.x + a.y + a.z + a.w;
        }
    }
    int sc = s;
#pragma unroll
    for (int off = 1; off < 32; off <<= 1) {
        int u = __shfl_up_sync(0xffffffffu, sc, off);
        if (lane >= off) sc += u;
    }
    if (lane == 31) wsum[wid] = sc;
    __syncthreads();
    if (wid == 0) {
        int ws = wsum[lane];
#pragma unroll
        for (int off = 1; off < 32; off <<= 1) {
            int u = __shfl_up_sync(0xffffffffu, ws, off);
            if (lane >= off) ws += u;
        }
        wsum[lane] = ws;
    }
    __syncthreads();
    if (t < 1000) {
        int run = sc - s + (wid ? wsum[wid - 1] : 0);
        int o[20];
#pragma unroll
        for (int i = 0; i < 20; i++) { o[i] = run; run += v[i]; }
        int4* dp = (int4*)(g_ptr + t * 20);
        int4* dc = (int4*)(g_cur + t * 20);
#pragma unroll
        for (int i = 0; i < 5; i++) {
            int4 a = make_int4(o[i * 4], o[i * 4 + 1], o[i * 4 + 2], o[i * 4 + 3]);
            dp[i] = a;
            dc[i] = a;
        }
    }
    if (t == 1023) g_ptr[NN] = wsum[31];
}

__global__ void fill_k(const int* __restrict__ ei) {
    int e = blockIdx.x * blockDim.x + threadIdx.x;
    if (e >= ET) return;
    int src, dst;
    if (e < EE) { src = ei[e]; dst = ei[EE + e]; }
    else        { src = dst = e - EE; }
    int p = atomicAdd(&g_cur[dst], 1);
    g_csrc[p] = src;
}

// ---------------- fp16 tensor-core GEMM (cp.async double-buffer) ----------
__device__ __forceinline__ void cpa16(unsigned int saddr, const void* g, int sz) {
    asm volatile("cp.async.cg.shared.global [%0], [%1], 16, %2;"
                 :: "r"(saddr), "l"(g), "r"(sz));
}

template <typename TC>
__global__ void __launch_bounds__(256, 2) gemm_tc_k(
    const __half* __restrict__ A, const __half* __restrict__ B,
    const float* __restrict__ bias, TC* __restrict__ C,
    int M, int N, int K,
    const float* __restrict__ asrc, const float* __restrict__ adst)
{
    extern __shared__ __half smh[];
    __half* Asb[2] = { smh, smh + ABUF_H };
    __half* Bsb[2] = { smh + 2 * ABUF_H, smh + 2 * ABUF_H + BBUF_H };

    int tid = threadIdx.x;
    int warp = tid >> 5, lane = tid & 31;
    int wm = (warp >> 2) * 64;
    int wn = (warp & 3) * 32;
    int bm = blockIdx.y * 128, bn = blockIdx.x * 128;

    auto loadA = [&](int buf, int k0) {
#pragma unroll
        for (int i = 0; i < 4; i++) {
            int f = tid + i * 256;
            int r = f >> 3, c8 = (f & 7) * 8;
            long grow = bm + r;
            int sz = (grow < M) ? 16 : 0;
            if (grow >= M) grow = M - 1;
            unsigned sa = (unsigned)__cvta_generic_to_shared(Asb[buf] + r * A_LDH + c8);
            cpa16(sa, A + grow * K + k0 + c8, sz);
        }
    };
    auto loadB = [&](int buf, int k0) {
#pragma unroll
        for (int i = 0; i < 4; i++) {
            int f = tid + i * 256;
            int kr = f >> 4, c8 = (f & 15) * 8;
            unsigned sa = (unsigned)__cvta_generic_to_shared(Bsb[buf] + kr * B_LDH + c8);
            cpa16(sa, B + (long)(k0 + kr) * N + bn + c8, 16);
        }
    };

    wmma::fragment<wmma::accumulator, 16, 16, 16, float> c[4][2];
#pragma unroll
    for (int mi = 0; mi < 4; mi++)
#pragma unroll
        for (int ni = 0; ni < 2; ni++)
            wmma::fill_fragment(c[mi][ni], 0.f);

    loadA(0, 0);
    loadB(0, 0);
    asm volatile("cp.async.commit_group;");
    asm volatile("cp.async.wait_group 0;" ::: "memory");
    __syncthreads();

    int nChunks = K / KCH;
    int buf = 0;
    for (int ch = 0; ch < nChunks; ch++) {
        if (ch + 1 < nChunks) {
            loadA(buf ^ 1, (ch + 1) * KCH);
            loadB(buf ^ 1, (ch + 1) * KCH);
            asm volatile("cp.async.commit_group;");
        }
#pragma unroll
        for (int ks = 0; ks < KCH / 16; ks++) {
            wmma::fragment<wmma::matrix_a, 16, 16, 16, __half, wmma::row_major> a[4];
            wmma::fragment<wmma::matrix_b, 16, 16, 16, __half, wmma::row_major> b[2];
#pragma unroll
            for (int mi = 0; mi < 4; mi++)
                wmma::load_matrix_sync(a[mi], Asb[buf] + (wm + mi * 16) * A_LDH + ks * 16, A_LDH);
#pragma unroll
            for (int ni = 0; ni < 2; ni++)
                wmma::load_matrix_sync(b[ni], Bsb[buf] + (ks * 16) * B_LDH + wn + ni * 16, B_LDH);
#pragma unroll
            for (int mi = 0; mi < 4; mi++)
#pragma unroll
                for (int ni = 0; ni < 2; ni++)
                    wmma::mma_sync(c[mi][ni], a[mi], b[ni], c[mi][ni]);
        }
        if (ch + 1 < nChunks) {
            asm volatile("cp.async.wait_group 0;" ::: "memory");
            __syncthreads();
            buf ^= 1;
        }
    }
    __syncthreads();

    float* s_al = (float*)smh + 3072;
    bool do_al = (asrc != nullptr);
    if (do_al) {
        if (tid < 256) s_al[tid] = 0.f;
        __syncthreads();
    }
    int h = blockIdx.x;

    float* bounce = (float*)smh + warp * 320;
    int er = lane >> 1;
    int ec = (lane & 1) * 8;
#pragma unroll
    for (int mi = 0; mi < 4; mi++) {
        float s1p = 0.f, s2p = 0.f;
#pragma unroll
        for (int ni = 0; ni < 2; ni++) {
            wmma::store_matrix_sync(bounce, c[mi][ni], 20, wmma::mem_row_major);
            __syncwarp();
            int grow = bm + wm + mi * 16 + er;
            if (grow < M) {
                int gcol = bn + wn + ni * 16 + ec;
                const float* srcb = &bounce[er * 20 + ec];
                float v[8];
#pragma unroll
                for (int j = 0; j < 8; j++)
                    v[j] = srcb[j] + (bias ? bias[gcol + j] : 0.f);
                if (do_al) {
                    int c0 = wn + ni * 16 + ec;
#pragma unroll
                    for (int j = 0; j < 8; j++) {
                        s1p += v[j] * asrc[h * CC + c0 + j];
                        s2p += v[j] * adst[h * CC + c0 + j];
                    }
                }
                TC* dst = &C[(long)grow * N + gcol];
                if constexpr (sizeof(TC) == 2) {
                    __half2 hb[4];
#pragma unroll
                    for (int j = 0; j < 4; j++)
                        hb[j] = __floats2half2_rn(v[2 * j], v[2 * j + 1]);
                    *(uint4*)dst = *(const uint4*)hb;
                } else {
                    *(float4*)&dst[0] = make_float4(v[0], v[1], v[2], v[3]);
                    *(float4*)&dst[4] = make_float4(v[4], v[5], v[6], v[7]);
                }
            }
            __syncwarp();
        }
        if (do_al) {
            s1p += __shfl_xor_sync(0xffffffffu, s1p, 1);
            s2p += __shfl_xor_sync(0xffffffffu, s2p, 1);
            if ((lane & 1) == 0) {
                int r = wm + mi * 16 + er;
                atomicAdd(&s_al[r], s1p);
                atomicAdd(&s_al[128 + r], s2p);
            }
        }
    }
    if (do_al) {
        __syncthreads();
        if (tid < 128) {
            int grow = bm + tid;
            if (grow < M) {
                g_als[grow * HH + h] = s_al[tid];
                g_ald[grow * HH + h] = s_al[128 + tid];
            }
        }
    }
}

// ---------------- aggregation: exp fused, half gathers, x4 unroll ---------
__global__ void agg_k(const __half* __restrict__ xlh, const float* __restrict__ bias,
                      float* __restrict__ out)
{
    int n = blockIdx.x;
    int t = threadIdx.x;
    int h = t >> 5;
    int lane = t & 31;
    int p0 = g_ptr[n], p1 = g_ptr[n + 1];
    float ad = g_ald[n * 4 + h];
    float4 acc = make_float4(0.f, 0.f, 0.f, 0.f);
    float s = 0.f;
    const __half* xh = xlh + h * CC + lane * 4;
    int p = p0;
    for (; p + 4 <= p1; p += 4) {
        int sidx[4];
        float w[4];
        uint2 u[4];
#pragma unroll
        for (int q = 0; q < 4; q++) sidx[q] = g_csrc[p + q];
#pragma unroll
        for (int q = 0; q < 4; q++) {
            float v = g_als[sidx[q] * 4 + h] + ad;
            v = v > 0.f ? v : 0.2f * v;
            w[q] = __expf(v);
            u[q] = *(const uint2*)(xh + (long)sidx[q] * DD);
        }
#pragma unroll
        for (int q = 0; q < 4; q++) {
            float2 a0 = __half22float2(*(__half2*)&u[q].x);
            float2 a1 = __half22float2(*(__half2*)&u[q].y);
            s += w[q];
            acc.x += w[q] * a0.x; acc.y += w[q] * a0.y;
            acc.z += w[q] * a1.x; acc.w += w[q] * a1.y;
        }
    }
    for (; p < p1; p++) {
        int sa = g_csrc[p];
        float va = g_als[sa * 4 + h] + ad;
        va = va > 0.f ? va : 0.2f * va;
        float wa = __expf(va);
        uint2 ua = *(const uint2*)(xh + (long)sa * DD);
        float2 a0 = __half22float2(*(__half2*)&ua.x);
        float2 a1 = __half22float2(*(__half2*)&ua.y);
        s += wa;
        acc.x += wa * a0.x; acc.y += wa * a0.y;
        acc.z += wa * a1.x; acc.w += wa * a1.y;
    }
    float inv = 1.f / (s + 1e-16f);
    int col = h * CC + lane * 4;
    float4 bv = *(const float4*)(bias + col);
    float4 o;
    o.x = acc.x * inv + bv.x;
    o.y = acc.y * inv + bv.y;
    o.z = acc.z * inv + bv.z;
    o.w = acc.w * inv + bv.w;
    *(float4*)(out + (long)n * DD + col) = o;
}

// ---------------- batch norm (fp32 stats) ----------------
__global__ void bn_stats_k(const float* __restrict__ h) {
    int t = threadIdx.x;
    int r0 = blockIdx.x * 50;
    float s = 0.f, s2 = 0.f;
    for (int i = 0; i < 50; i++) {
        int r = r0 + i;
        if (r < NN) {
            float v = h[(long)r * DD + t];
            s += v;
            s2 += v * v;
        }
    }
    atomicAdd(&g_sumf[t], s);
    atomicAdd(&g_sqf[t], s2);
}

__global__ void bn_fin_k(const float* __restrict__ g, const float* __restrict__ b) {
    int t = threadIdx.x;
    float mean = g_sumf[t] * (1.f / NN);
    float var  = g_sqf[t] * (1.f / NN) - mean * mean;
    float a = g[t] * rsqrtf(var + 1e-5f);
    g_scale[t] = a;
    g_shift[t] = b[t] - mean * a;
    g_sumf[t] = 0.f;
    g_sqf[t]  = 0.f;
}

__global__ void bn_apply_k(const float4* __restrict__ in, const float4* __restrict__ res,
                           float4* __restrict__ out, __half2* __restrict__ outh)
{
    int i = blockIdx.x * blockDim.x + threadIdx.x;
    if (i >= NN * DD / 4) return;
    int j = (i * 4) & (DD - 1);
    float4 v = in[i];
    v.x = v.x * g_scale[j + 0] + g_shift[j + 0];
    v.y = v.y * g_scale[j + 1] + g_shift[j + 1];
    v.z = v.z * g_scale[j + 2] + g_shift[j + 2];
    v.w = v.w * g_scale[j + 3] + g_shift[j + 3];
    v.x = v.x > 0.f ? v.x : 0.01f * v.x;
    v.y = v.y > 0.f ? v.y : 0.01f * v.y;
    v.z = v.z > 0.f ? v.z : 0.01f * v.z;
    v.w = v.w > 0.f ? v.w : 0.01f * v.w;
    if (res) {
        float4 r = res[i];
        v.x += r.x; v.y += r.y; v.z += r.z; v.w += r.w;
    }
    if (out) out[i] = v;
    outh[i * 2 + 0] = __floats2half2_rn(v.x, v.y);
    outh[i * 2 + 1] = __floats2half2_rn(v.z, v.w);
}

// ---------------- launch ----------------
extern "C" void kernel_launch(void* const* d_in, const int* in_sizes, int n_in,
                              void* d_out, int out_size)
{
    const float* X    = (const float*)d_in[0];
    const int*   ei   = (const int*)d_in[1];
    const float* pos  = (const float*)d_in[3];
    const float* W1   = (const float*)d_in[4];
    const float* as1  = (const float*)d_in[5];
    const float* ad1  = (const float*)d_in[6];
    const float* b1   = (const float*)d_in[7];
    const float* W2   = (const float*)d_in[8];
    const float* as2  = (const float*)d_in[9];
    const float* ad2  = (const float*)d_in[10];
    const float* b2   = (const float*)d_in[11];
    const float* bn1g = (const float*)d_in[12];
    const float* bn1b = (const float*)d_in[13];
    const float* bn2g = (const float*)d_in[14];
    const float* bn2b = (const float*)d_in[15];
    const float* outW = (const float*)d_in[18];
    const float* outb = (const float*)d_in[19];
    float*       out  = (float*)d_out;

    float *h, *hn;
    __half *xlh, *xph, *w1h, *w2h, *owh, *hnh, *hh;
    cudaGetSymbolAddress((void**)&h,   g_h);
    cudaGetSymbolAddress((void**)&hn,  g_hn);
    cudaGetSymbolAddress((void**)&xlh, g_xlh);
    cudaGetSymbolAddress((void**)&xph, g_xph);
    cudaGetSymbolAddress((void**)&w1h, g_w1h);
    cudaGetSymbolAddress((void**)&w2h, g_w2h);
    cudaGetSymbolAddress((void**)&owh, g_owh);
    cudaGetSymbolAddress((void**)&hnh, g_hnh);
    cudaGetSymbolAddress((void**)&hh,  g_hh);

    cudaFuncSetAttribute(gemm_tc_k<__half>, cudaFuncAttributeMaxDynamicSharedMemorySize,
                         GEMM_SMEM_BYTES);
    cudaFuncSetAttribute(gemm_tc_k<float>, cudaFuncAttributeMaxDynamicSharedMemorySize,
                         GEMM_SMEM_BYTES);

    const int EB = (ET + 255) / 256;
    dim3 gGat(DD / 128, (NN + 127) / 128);
    dim3 gOut(OUTD / 128, (NN + 127) / 128);
    int bnApBlocks = (NN * DD / 4 + 255) / 256;
    int bnBlocks = (NN + 49) / 50;
    int nW = 128 * DD + DD * DD + DD * OUTD;

    // side stream: CSR build only (R15 ordering)
    cudaStream_t s2;
    cudaStreamCreateWithFlags(&s2, cudaStreamNonBlocking);
    cudaEvent_t eFork, eJoin;
    cudaEventCreateWithFlags(&eFork, cudaEventDisableTiming);
    cudaEventCreateWithFlags(&eJoin, cudaEventDisableTiming);

    cudaEventRecord(eFork, 0);
    cudaStreamWaitEvent(s2, eFork, 0);

    zero_cnt_k<<<(NN + 255) / 256, 256, 0, s2>>>();
    count_k<<<EB, 256, 0, s2>>>(ei);
    scan_k<<<1, 1024, 0, s2>>>();
    fill_k<<<EB, 256, 0, s2>>>(ei);
    cudaEventRecord(eJoin, s2);

    // main stream: pack/convert + gemm1 (with fused attention dots)
    pack_k<<<(NN * 128 + 255) / 256, 256>>>(X, pos);
    cvtw_k<<<(nW + 255) / 256, 256>>>(W1, W2, outW);
    gemm_tc_k<__half><<<gGat, 256, GEMM_SMEM_BYTES>>>(xph, w1h, nullptr, xlh,
                                                      NN, DD, 128, as1, ad1);

    cudaStreamWaitEvent(0, eJoin, 0);   // join: agg needs CSR

    // ---- layer 1 rest ----
    agg_k<<<NN, 128>>>(xlh, b1, h);
    bn_stats_k<<<bnBlocks, 512>>>(h);
    bn_fin_k<<<1, 512>>>(bn1g, bn1b);
    bn_apply_k<<<bnApBlocks, 256>>>((const float4*)h, nullptr, (float4*)hn, (__half2*)hnh);

    // ---- layer 2 ----
    gemm_tc_k<__half><<<gGat, 256, GEMM_SMEM_BYTES>>>(hnh, w2h, nullptr, xlh,
                                                      NN, DD, DD, as2, ad2);
    agg_k<<<NN, 128>>>(xlh, b2, h);
    bn_stats_k<<<bnBlocks, 512>>>(h);
    bn_fin_k<<<1, 512>>>(bn2g, bn2b);
    bn_apply_k<<<bnApBlocks, 256>>>((const float4*)h, (const float4*)hn, nullptr, (__half2*)hh);

    // ---- output projection ----
    gemm_tc_k<float><<<gOut, 256, GEMM_SMEM_BYTES>>>(hh, owh, outb, out,
                                                     NN, OUTD, DD, nullptr, nullptr);

    cudaEventDestroy(eFork);
    cudaEventDestroy(eJoin);
    cudaStreamDestroy(s2);
}